// round 3
// baseline (speedup 1.0000x reference)
#include <cuda_runtime.h>
#include <cstdint>

// CausalConv1d: out[b,h] = state[b,h,0]*w[h,0] + state[b,h,1]*w[h,1]
//                        + state[b,h,2]*w[h,2] + x[b,h]*w[h,3] + bias[h]
// new_state[b,h,:] = {state[b,h,1], state[b,h,2], x[b,h]}
//
// R3: batch-loop restructure. Each thread owns 4 fixed h's and iterates over
// R=8 batch rows, so the 80B of weight+bias loads amortize 8x (L1 was
// co-binding with DRAM at 67% in R2). Streaming tensors use .cs hints.

#define HIDDEN 4096
#define BATCH  4096
#define PAIRS  ((int64_t)BATCH * HIDDEN)
#define HGROUPS (HIDDEN / 4)        // 1024 column groups of 4 h's
#define ROWS_PER_THREAD 8

__device__ __forceinline__ float4 ldcs4(const float* p) {
    return __ldcs(reinterpret_cast<const float4*>(p));
}
__device__ __forceinline__ void stcs4(float* p, float4 v) {
    __stcs(reinterpret_cast<float4*>(p), v);
}

__global__ void __launch_bounds__(256, 8)
causal_conv1d_kernel(const float* __restrict__ x,
                     const float* __restrict__ state,
                     const float* __restrict__ weight,   // [HIDDEN,4]
                     const float* __restrict__ bias,     // [HIDDEN]
                     float* __restrict__ out,            // [BATCH,HIDDEN]
                     float* __restrict__ new_state)      // [BATCH,HIDDEN,3]
{
    // blockIdx.x in [0, HGROUPS/256): which quarter of the hidden dim
    // blockIdx.y in [0, BATCH/ROWS_PER_THREAD): which batch tile
    const int g  = blockIdx.x * blockDim.x + threadIdx.x;   // column group [0,1024)
    const int h0 = g << 2;                                   // first of 4 h's
    const int b0 = blockIdx.y * ROWS_PER_THREAD;

    // ---- load weights/bias ONCE (L1/L2 resident, reused across 8 rows) ----
    const float4 w0 = *reinterpret_cast<const float4*>(weight + (int64_t)(h0 + 0) * 4);
    const float4 w1 = *reinterpret_cast<const float4*>(weight + (int64_t)(h0 + 1) * 4);
    const float4 w2 = *reinterpret_cast<const float4*>(weight + (int64_t)(h0 + 2) * 4);
    const float4 w3 = *reinterpret_cast<const float4*>(weight + (int64_t)(h0 + 3) * 4);
    const float4 bv = *reinterpret_cast<const float4*>(bias + h0);

    int64_t p0 = (int64_t)b0 * HIDDEN + h0;   // first pair index for row b0

    #pragma unroll 2
    for (int r = 0; r < ROWS_PER_THREAD; ++r, p0 += HIDDEN) {
        // ---- streaming loads (16B aligned, fully coalesced, evict-first) ----
        const float4 xv = ldcs4(x + p0);
        const float*  sb = state + p0 * 3;
        const float4 s0 = ldcs4(sb + 0);   // S0..S3
        const float4 s1 = ldcs4(sb + 4);   // S4..S7
        const float4 s2 = ldcs4(sb + 8);   // S8..S11

        // ---- compute: pair j uses S[3j..3j+2] and X[j] ----
        float4 ov;
        ov.x = fmaf(s0.x, w0.x, fmaf(s0.y, w0.y, fmaf(s0.z, w0.z, fmaf(xv.x, w0.w, bv.x))));
        ov.y = fmaf(s0.w, w1.x, fmaf(s1.x, w1.y, fmaf(s1.y, w1.z, fmaf(xv.y, w1.w, bv.y))));
        ov.z = fmaf(s1.z, w2.x, fmaf(s1.w, w2.y, fmaf(s2.x, w2.z, fmaf(xv.z, w2.w, bv.z))));
        ov.w = fmaf(s2.y, w3.x, fmaf(s2.z, w3.y, fmaf(s2.w, w3.z, fmaf(xv.w, w3.w, bv.w))));

        // ---- new_state flat = {S1,S2,X0, S4,S5,X1, S7,S8,X2, S10,S11,X3} ----
        const float4 ns0 = make_float4(s0.y, s0.z, xv.x, s1.x);
        const float4 ns1 = make_float4(s1.y, xv.y, s1.w, s2.x);
        const float4 ns2 = make_float4(xv.z, s2.z, s2.w, xv.w);

        // ---- streaming stores ----
        stcs4(out + p0, ov);
        float* nb = new_state + p0 * 3;
        stcs4(nb + 0, ns0);
        stcs4(nb + 4, ns1);
        stcs4(nb + 8, ns2);
    }
}

extern "C" void kernel_launch(void* const* d_in, const int* in_sizes, int n_in,
                              void* d_out, int out_size)
{
    const float* x      = (const float*)d_in[0];
    const float* state  = (const float*)d_in[1];
    const float* weight = (const float*)d_in[2];
    const float* bias   = (const float*)d_in[3];

    float* out       = (float*)d_out;
    float* new_state = (float*)d_out + PAIRS;

    dim3 block(256);
    dim3 grid(HGROUPS / 256, BATCH / ROWS_PER_THREAD);   // (4, 512) = 2048 blocks
    causal_conv1d_kernel<<<grid, block>>>(x, state, weight, bias, out, new_state);
}